// round 9
// baseline (speedup 1.0000x reference)
#include <cuda_runtime.h>
#include <cuda_bf16.h>
#include <math.h>
#include <stdint.h>

#define NB 8
#define NL 48
#define NT 512
#define HD 128
#define NG 10
#define M_TOTAL (NB*NL*NT)          // 196608

#define OFF_PI  0
#define OFF_SIG (M_TOTAL*NG)
#define OFF_MU  (2*M_TOTAL*NG)
#define OFF_D   (3*M_TOTAL*NG)
#define OFF_CB  (3*M_TOTAL*NG + M_TOTAL)

// scratch (device globals: no allocation)
__device__ float g_Al[NB*NL*HD];    // 384 x 128
__device__ float g_At[NB*NT*HD];    // 4096 x 128

__device__ __forceinline__ float elu1(float x) {
    return x > 0.0f ? x : (__expf(x) - 1.0f);
}

// split two fp32 into bf16 hi (truncate) + bf16 lo (round of residual),
// packed k-adjacent: {lo16 = elem k, hi16 = elem k+1}
__device__ __forceinline__ void split2(float e0, float e1, uint32_t& hi, uint32_t& lo) {
    uint32_t u0 = __float_as_uint(e0) & 0xffff0000u;
    uint32_t u1 = __float_as_uint(e1) & 0xffff0000u;
    hi = __byte_perm(u0, u1, 0x7632);
    float f0 = e0 - __uint_as_float(u0);
    float f1 = e1 - __uint_as_float(u1);
    asm("cvt.rn.bf16x2.f32 %0, %1, %2;" : "=r"(lo) : "f"(f1), "f"(f0));
}

// warp-level bf16 MMA, d += a*b  (baseline PTX, works on plain sm_103 target)
__device__ __forceinline__ void mma_bf16(float* d, const uint32_t* a, const uint32_t* b) {
    asm volatile("mma.sync.aligned.m16n8k16.row.col.f32.bf16.bf16.f32 "
        "{%0,%1,%2,%3}, {%4,%5,%6,%7}, {%8,%9}, {%0,%1,%2,%3};"
        : "+f"(d[0]), "+f"(d[1]), "+f"(d[2]), "+f"(d[3])
        : "r"(a[0]), "r"(a[1]), "r"(a[2]), "r"(a[3]), "r"(b[0]), "r"(b[1]));
}

// ---------------------------------------------------------------------------
// Precompute: A_l = s*(lig_s@W1^T + b1 - mean) + beta ;  A_t = s*(pro_s@W1^T)
// 512 threads; warp = 8 output dims x 32 rows -> W reads are warp-uniform
// broadcasts (LDS.128); Xs pitch 129 -> conflict-free column reads.
// ---------------------------------------------------------------------------
#define PRE_ROWS 32
#define PRE_THREADS 512
#define XS_P  129
#define W1T_P 132
#define PRE_SMEM ((PRE_ROWS*XS_P + HD*W1T_P)*sizeof(float))   // 84096 B

__global__ void __launch_bounds__(PRE_THREADS)
precompute_kernel(const float* __restrict__ lig_s, const float* __restrict__ pro_s,
                  const float* __restrict__ W1,    const float* __restrict__ b1,
                  const float* __restrict__ bn_g,  const float* __restrict__ bn_b,
                  const float* __restrict__ bn_m,  const float* __restrict__ bn_v)
{
    extern __shared__ float sm[];
    float* Xs  = sm;                      // [32][129]
    float* W1t = sm + PRE_ROWS*XS_P;      // [128][132] transposed

    const int tid  = threadIdx.x;
    const int w    = tid >> 5;            // 0..15
    const int ln   = tid & 31;
    const int row0 = blockIdx.x * PRE_ROWS;
    const bool is_lig = (row0 < NB*NL);

    const float4* src = is_lig ? (const float4*)(lig_s + (size_t)row0*HD)
                               : (const float4*)(pro_s + (size_t)(row0 - NB*NL)*HD);
    #pragma unroll
    for (int i = 0; i < 2; i++) {
        int idx = tid + i*PRE_THREADS;    // < 1024
        float4 v = src[idx];
        int r = idx >> 5, c = (idx & 31) << 2;
        Xs[r*XS_P + c]   = v.x;
        Xs[r*XS_P + c+1] = v.y;
        Xs[r*XS_P + c+2] = v.z;
        Xs[r*XS_P + c+3] = v.w;
    }
    #pragma unroll
    for (int i = 0; i < (HD*HD)/PRE_THREADS; i++) {
        int idx = tid + i*PRE_THREADS;
        int h = idx >> 7, k = idx & (HD-1);
        W1t[k*W1T_P + h] = W1[idx];
    }
    __syncthreads();

    const int h0 = w << 3;
    const float* xrow = Xs + ln*XS_P;
    float acc[8];
    #pragma unroll
    for (int j = 0; j < 8; j++) acc[j] = 0.0f;

    #pragma unroll 4
    for (int k = 0; k < HD; k++) {
        float x = xrow[k];
        float4 wa = *(const float4*)(W1t + k*W1T_P + h0);      // uniform -> bcast
        float4 wb = *(const float4*)(W1t + k*W1T_P + h0 + 4);
        acc[0] = fmaf(x, wa.x, acc[0]);
        acc[1] = fmaf(x, wa.y, acc[1]);
        acc[2] = fmaf(x, wa.z, acc[2]);
        acc[3] = fmaf(x, wa.w, acc[3]);
        acc[4] = fmaf(x, wb.x, acc[4]);
        acc[5] = fmaf(x, wb.y, acc[5]);
        acc[6] = fmaf(x, wb.z, acc[6]);
        acc[7] = fmaf(x, wb.w, acc[7]);
    }

    const int row = row0 + ln;
    float o[8];
    if (is_lig) {
        #pragma unroll
        for (int j = 0; j < 8; j++) {
            int h = h0 + j;
            float s = bn_g[h] * rsqrtf(bn_v[h] + 1e-5f);
            o[j] = s * (acc[j] + b1[h] - bn_m[h]) + bn_b[h];
        }
        float4* dst = (float4*)(g_Al + (size_t)row*HD + h0);
        dst[0] = make_float4(o[0], o[1], o[2], o[3]);
        dst[1] = make_float4(o[4], o[5], o[6], o[7]);
    } else {
        #pragma unroll
        for (int j = 0; j < 8; j++) {
            int h = h0 + j;
            float s = bn_g[h] * rsqrtf(bn_v[h] + 1e-5f);
            o[j] = s * acc[j];
        }
        float4* dst = (float4*)(g_At + (size_t)(row - NB*NL)*HD + h0);
        dst[0] = make_float4(o[0], o[1], o[2], o[3]);
        dst[1] = make_float4(o[4], o[5], o[6], o[7]);
    }
}

// ---------------------------------------------------------------------------
// Pair kernel via mma.sync (HMMA bf16, 2-term split, 3 passes).
// Block = 8 ligands x 32 proteins, 8 warps, warp = 1 lig x 32 prot.
// R9: (256,4) no-spill config; W hi/lo fused into one uint4 (single LDS.128
// per (kc,nc), shared across both mt); fully unrolled kc loop.
// ---------------------------------------------------------------------------
#define THREADS 256
#define AT_P 136              // float pitch for At/Al staging (mod 32 == 8)

// smem float offsets — F_D overlaps [F_AT..F_W) (operands dead after mainloop)
#define F_AT   0              // 32 x 136 = 4352
#define F_AL   4352           // 8 x 136 = 1088
#define F_W    5440           // [kc 8][nc 4][lane 32] uint4 = 4096 floats
#define F_D    0              // 256 x 34 = 8704  (union)
#define F_BIAS 9536           // 32
#define F_PL   9568           // 8 x 4
#define F_PT   9600           // 32 x 4
#define SMF    9728           // floats -> 38912 bytes

__device__ __forceinline__ float wval(int n, int k, const float* __restrict__ wp,
                                      const float* __restrict__ ws,
                                      const float* __restrict__ wm) {
    if (n < 10) return wp[n*HD + k];
    if (n < 20) return ws[(n-10)*HD + k];
    if (n < 30) return wm[(n-20)*HD + k];
    return 0.0f;
}

__global__ void __launch_bounds__(THREADS, 4)
pair_kernel(const float* __restrict__ lig_pos, const float* __restrict__ pro_pos,
            const float* __restrict__ W_pi,  const float* __restrict__ b_pi,
            const float* __restrict__ W_sig, const float* __restrict__ b_sig,
            const float* __restrict__ W_mu,  const float* __restrict__ b_mu,
            float* __restrict__ out)
{
    extern __shared__ float sm[];
    const int tid  = threadIdx.x;
    const int w    = tid >> 5;           // warp = local ligand 0..7
    const int lane = tid & 31;
    const int r    = lane >> 2;          // 0..7
    const int q    = lane & 3;           // 0..3
    const int b    = blockIdx.z;
    const int l0   = blockIdx.y * 8;
    const int t0   = blockIdx.x * 32;

    // ---- stage At (32 rows) and Al (8 rows), fp32, pitch 136 ----
    {
        const float4* src = (const float4*)(g_At + (size_t)(b*NT + t0)*HD);
        float4* dst = (float4*)&sm[F_AT];          // pitch 34 float4
        #pragma unroll
        for (int i = 0; i < 4; i++) {
            int idx = tid + i*THREADS;              // < 1024
            dst[(idx >> 5)*34 + (idx & 31)] = src[idx];
        }
    }
    {
        const float4* src = (const float4*)(g_Al + (size_t)(b*NL + l0)*HD);
        float4* dst = (float4*)&sm[F_AL];
        dst[(tid >> 5)*34 + (tid & 31)] = src[tid]; // 256 float4
    }
    // ---- pre-split W into per-lane B fragments: uint4 {hi0,hi1,lo0,lo1} ----
    {
        uint4* wd = (uint4*)&sm[F_W];
        #pragma unroll
        for (int e = 0; e < 4; e++) {
            int idx = tid + e*THREADS;              // < 1024 = [kc 8][nc 4][lane 32]
            int kc = idx >> 7, nc = (idx >> 5) & 3, ln = idx & 31;
            int n = nc*8 + (ln >> 2);
            int k = kc*16 + 2*(ln & 3);
            float w0 = wval(n, k,   W_pi, W_sig, W_mu);
            float w1 = wval(n, k+1, W_pi, W_sig, W_mu);
            float w8 = wval(n, k+8, W_pi, W_sig, W_mu);
            float w9 = wval(n, k+9, W_pi, W_sig, W_mu);
            uint32_t h0, lo0, h1, lo1;
            split2(w0, w1, h0, lo0);
            split2(w8, w9, h1, lo1);
            wd[idx] = make_uint4(h0, h1, lo0, lo1);
        }
    }
    if (tid < NG) {
        sm[F_BIAS + tid]      = b_pi[tid];
        sm[F_BIAS + 10 + tid] = b_sig[tid];
        sm[F_BIAS + 20 + tid] = b_mu[tid];
    }
    if (tid < 24) {
        int l = tid / 3, c = tid % 3;
        sm[F_PL + l*4 + c] = lig_pos[(size_t)(b*NL + l0 + l)*3 + c];
    }
    if (tid < 96) {
        int t = tid / 3, c = tid % 3;
        sm[F_PT + t*4 + c] = pro_pos[(size_t)(b*NT + t0 + t)*3 + c];
    }
    __syncthreads();

    // ---- mainloop: warp computes D[32 pairs][32 heads] for its ligand ----
    float D[2][4][4];
    #pragma unroll
    for (int mt = 0; mt < 2; mt++)
        #pragma unroll
        for (int nc = 0; nc < 4; nc++)
            #pragma unroll
            for (int j = 0; j < 4; j++) D[mt][nc][j] = 0.0f;

    const float* alr = &sm[F_AL + w*AT_P + 2*q];
    const float* atr = &sm[F_AT + r*AT_P + 2*q];
    const uint4* wl4 = (const uint4*)&sm[F_W] + lane;

    #pragma unroll
    for (int kc = 0; kc < 8; kc++) {
        const int kb = kc*16;
        float2 L0 = *(const float2*)(alr + kb);
        float2 L8 = *(const float2*)(alr + kb + 8);
        uint32_t ah[2][4], av[2][4];
        #pragma unroll
        for (int mt = 0; mt < 2; mt++) {
            const float* at0 = atr + mt*16*AT_P;
            float2 t00 = *(const float2*)(at0 + kb);
            float2 t08 = *(const float2*)(at0 + kb + 8);
            float2 t80 = *(const float2*)(at0 + 8*AT_P + kb);
            float2 t88 = *(const float2*)(at0 + 8*AT_P + kb + 8);
            split2(elu1(t00.x + L0.x), elu1(t00.y + L0.y), ah[mt][0], av[mt][0]);
            split2(elu1(t80.x + L0.x), elu1(t80.y + L0.y), ah[mt][1], av[mt][1]);
            split2(elu1(t08.x + L8.x), elu1(t08.y + L8.y), ah[mt][2], av[mt][2]);
            split2(elu1(t88.x + L8.x), elu1(t88.y + L8.y), ah[mt][3], av[mt][3]);
        }
        #pragma unroll
        for (int nc = 0; nc < 4; nc++) {
            uint4 wv = wl4[(kc*4 + nc)*32];
            uint32_t bh[2] = {wv.x, wv.y};
            uint32_t bl[2] = {wv.z, wv.w};
            mma_bf16(D[0][nc], ah[0], bh);
            mma_bf16(D[1][nc], ah[1], bh);
            mma_bf16(D[0][nc], ah[0], bl);
            mma_bf16(D[1][nc], ah[1], bl);
            mma_bf16(D[0][nc], av[0], bh);
            mma_bf16(D[1][nc], av[1], bh);
        }
    }

    // operands (At/Al/W) dead from here; D buffer overlaps them
    __syncthreads();

    // ---- D fragments -> smem (pair-major, pitch 34) ----
    #pragma unroll
    for (int mt = 0; mt < 2; mt++) {
        const int p = w*32 + mt*16 + r;
        #pragma unroll
        for (int nc = 0; nc < 4; nc++) {
            *(float2*)&sm[F_D + p*34 + nc*8 + 2*q]     = make_float2(D[mt][nc][0], D[mt][nc][1]);
            *(float2*)&sm[F_D + (p+8)*34 + nc*8 + 2*q] = make_float2(D[mt][nc][2], D[mt][nc][3]);
        }
    }
    __syncthreads();

    // ---- per-pair epilogue: softmax / elu heads / dist, written back in-place ----
    {
        float* row = &sm[F_D + tid*34];
        float rr[30];
        #pragma unroll
        for (int g = 0; g < 30; g++) rr[g] = row[g];
        float y[10], mx = -1e30f;
        #pragma unroll
        for (int g = 0; g < NG; g++) { y[g] = rr[g] + sm[F_BIAS + g]; mx = fmaxf(mx, y[g]); }
        float ssum = 0.0f;
        #pragma unroll
        for (int g = 0; g < NG; g++) { y[g] = __expf(y[g] - mx); ssum += y[g]; }
        float inv = 1.0f / ssum;
        #pragma unroll
        for (int g = 0; g < NG; g++) row[g] = y[g]*inv;
        #pragma unroll
        for (int g = 0; g < NG; g++) row[10+g] = elu1(rr[10+g] + sm[F_BIAS + 10 + g]) + 1.1f;
        #pragma unroll
        for (int g = 0; g < NG; g++) row[20+g] = elu1(rr[20+g] + sm[F_BIAS + 20 + g]) + 1.0f;
        const int ll = tid >> 5, tl = tid & 31;
        float dx = sm[F_PL + ll*4]   - sm[F_PT + tl*4];
        float dy = sm[F_PL + ll*4+1] - sm[F_PT + tl*4+1];
        float dz = sm[F_PL + ll*4+2] - sm[F_PT + tl*4+2];
        row[30] = sqrtf(dx*dx + dy*dy + dz*dz);
    }
    __syncthreads();

    // ---- coalesced copy-out: pi / sigma / mu (3 x 8 ligs x 320 floats) ----
    #pragma unroll
    for (int i = 0; i < 30; i++) {
        int idx = tid + i*THREADS;          // exactly 7680 total
        int sec = idx / 2560;
        int rem = idx - sec*2560;
        int llc = rem / 320;
        int r2  = rem - llc*320;
        int t   = r2 / 10;
        int g   = r2 - t*10;
        size_t secoff = (sec == 0) ? (size_t)OFF_PI : (sec == 1) ? (size_t)OFF_SIG : (size_t)OFF_MU;
        size_t gaddr = secoff + ((size_t)((b*NL + l0 + llc)*NT) + t0 + t)*NG + g;
        out[gaddr] = sm[F_D + (llc*32 + t)*34 + sec*10 + g];
    }
    // dist + batch id
    {
        size_t pg = (size_t)((b*NL + l0 + (tid >> 5))*NT) + t0 + (tid & 31);
        out[OFF_D  + pg] = sm[F_D + tid*34 + 30];
        out[OFF_CB + pg] = (float)b;
    }
}

// ---------------------------------------------------------------------------
extern "C" void kernel_launch(void* const* d_in, const int* in_sizes, int n_in,
                              void* d_out, int out_size)
{
    (void)in_sizes; (void)n_in; (void)out_size;
    const float* lig_s   = (const float*)d_in[0];
    const float* lig_pos = (const float*)d_in[1];
    const float* pro_s   = (const float*)d_in[3];
    const float* pro_pos = (const float*)d_in[4];
    const float* W1      = (const float*)d_in[6];
    const float* b1      = (const float*)d_in[7];
    const float* bn_g    = (const float*)d_in[8];
    const float* bn_b    = (const float*)d_in[9];
    const float* bn_m    = (const float*)d_in[10];
    const float* bn_v    = (const float*)d_in[11];
    const float* W_pi    = (const float*)d_in[12];
    const float* b_pi    = (const float*)d_in[13];
    const float* W_sig   = (const float*)d_in[14];
    const float* b_sig   = (const float*)d_in[15];
    const float* W_mu    = (const float*)d_in[16];
    const float* b_mu    = (const float*)d_in[17];
    float* out = (float*)d_out;

    cudaFuncSetAttribute(precompute_kernel,
                         cudaFuncAttributeMaxDynamicSharedMemorySize, (int)PRE_SMEM);
    precompute_kernel<<<(NB*NL + NB*NT)/PRE_ROWS, PRE_THREADS, PRE_SMEM>>>(
        lig_s, pro_s, W1, b1, bn_g, bn_b, bn_m, bn_v);

    pair_kernel<<<dim3(NT/32, NL/8, NB), THREADS, SMF*sizeof(float)>>>(
        lig_pos, pro_pos, W_pi, b_pi, W_sig, b_sig, W_mu, b_mu, out);
}

// round 10
// speedup vs baseline: 1.3692x; 1.3692x over previous
#include <cuda_runtime.h>
#include <cuda_bf16.h>
#include <math.h>
#include <stdint.h>

#define NB 8
#define NL 48
#define NT 512
#define HD 128
#define NG 10
#define M_TOTAL (NB*NL*NT)          // 196608

#define OFF_PI  0
#define OFF_SIG (M_TOTAL*NG)
#define OFF_MU  (2*M_TOTAL*NG)
#define OFF_D   (3*M_TOTAL*NG)
#define OFF_CB  (3*M_TOTAL*NG + M_TOTAL)

// scratch (device globals: no allocation)
__device__ float g_Al[NB*NL*HD];    // 384 x 128
__device__ float g_At[NB*NT*HD];    // 4096 x 128

__device__ __forceinline__ float elu1(float x) {
    return x > 0.0f ? x : (__expf(x) - 1.0f);
}

// split two fp32 into bf16 hi (truncate) + bf16 lo (round of residual),
// packed k-adjacent: {lo16 = elem k, hi16 = elem k+1}
__device__ __forceinline__ void split2(float e0, float e1, uint32_t& hi, uint32_t& lo) {
    uint32_t u0 = __float_as_uint(e0) & 0xffff0000u;
    uint32_t u1 = __float_as_uint(e1) & 0xffff0000u;
    hi = __byte_perm(u0, u1, 0x7632);
    float f0 = e0 - __uint_as_float(u0);
    float f1 = e1 - __uint_as_float(u1);
    asm("cvt.rn.bf16x2.f32 %0, %1, %2;" : "=r"(lo) : "f"(f1), "f"(f0));
}

// warp-level bf16 MMA, d += a*b  (baseline PTX, works on plain sm_103 target)
__device__ __forceinline__ void mma_bf16(float* d, const uint32_t* a, const uint32_t* b) {
    asm volatile("mma.sync.aligned.m16n8k16.row.col.f32.bf16.bf16.f32 "
        "{%0,%1,%2,%3}, {%4,%5,%6,%7}, {%8,%9}, {%0,%1,%2,%3};"
        : "+f"(d[0]), "+f"(d[1]), "+f"(d[2]), "+f"(d[3])
        : "r"(a[0]), "r"(a[1]), "r"(a[2]), "r"(a[3]), "r"(b[0]), "r"(b[1]));
}

// ---------------------------------------------------------------------------
// Precompute: A_l = s*(lig_s@W1^T + b1 - mean) + beta ;  A_t = s*(pro_s@W1^T)
// ---------------------------------------------------------------------------
#define PRE_ROWS 32
#define PRE_THREADS 512
#define XS_P  129
#define W1T_P 132
#define PRE_SMEM ((PRE_ROWS*XS_P + HD*W1T_P)*sizeof(float))   // 84096 B

__global__ void __launch_bounds__(PRE_THREADS)
precompute_kernel(const float* __restrict__ lig_s, const float* __restrict__ pro_s,
                  const float* __restrict__ W1,    const float* __restrict__ b1,
                  const float* __restrict__ bn_g,  const float* __restrict__ bn_b,
                  const float* __restrict__ bn_m,  const float* __restrict__ bn_v)
{
    extern __shared__ float sm[];
    float* Xs  = sm;                      // [32][129]
    float* W1t = sm + PRE_ROWS*XS_P;      // [128][132] transposed

    const int tid  = threadIdx.x;
    const int w    = tid >> 5;            // 0..15
    const int ln   = tid & 31;
    const int row0 = blockIdx.x * PRE_ROWS;
    const bool is_lig = (row0 < NB*NL);

    const float4* src = is_lig ? (const float4*)(lig_s + (size_t)row0*HD)
                               : (const float4*)(pro_s + (size_t)(row0 - NB*NL)*HD);
    #pragma unroll
    for (int i = 0; i < 2; i++) {
        int idx = tid + i*PRE_THREADS;    // < 1024
        float4 v = src[idx];
        int r = idx >> 5, c = (idx & 31) << 2;
        Xs[r*XS_P + c]   = v.x;
        Xs[r*XS_P + c+1] = v.y;
        Xs[r*XS_P + c+2] = v.z;
        Xs[r*XS_P + c+3] = v.w;
    }
    #pragma unroll
    for (int i = 0; i < (HD*HD)/PRE_THREADS; i++) {
        int idx = tid + i*PRE_THREADS;
        int h = idx >> 7, k = idx & (HD-1);
        W1t[k*W1T_P + h] = W1[idx];
    }
    __syncthreads();

    const int h0 = w << 3;
    const float* xrow = Xs + ln*XS_P;
    float acc[8];
    #pragma unroll
    for (int j = 0; j < 8; j++) acc[j] = 0.0f;

    #pragma unroll 4
    for (int k = 0; k < HD; k++) {
        float x = xrow[k];
        float4 wa = *(const float4*)(W1t + k*W1T_P + h0);      // uniform -> bcast
        float4 wb = *(const float4*)(W1t + k*W1T_P + h0 + 4);
        acc[0] = fmaf(x, wa.x, acc[0]);
        acc[1] = fmaf(x, wa.y, acc[1]);
        acc[2] = fmaf(x, wa.z, acc[2]);
        acc[3] = fmaf(x, wa.w, acc[3]);
        acc[4] = fmaf(x, wb.x, acc[4]);
        acc[5] = fmaf(x, wb.y, acc[5]);
        acc[6] = fmaf(x, wb.z, acc[6]);
        acc[7] = fmaf(x, wb.w, acc[7]);
    }

    const int row = row0 + ln;
    float o[8];
    if (is_lig) {
        #pragma unroll
        for (int j = 0; j < 8; j++) {
            int h = h0 + j;
            float s = bn_g[h] * rsqrtf(bn_v[h] + 1e-5f);
            o[j] = s * (acc[j] + b1[h] - bn_m[h]) + bn_b[h];
        }
        float4* dst = (float4*)(g_Al + (size_t)row*HD + h0);
        dst[0] = make_float4(o[0], o[1], o[2], o[3]);
        dst[1] = make_float4(o[4], o[5], o[6], o[7]);
    } else {
        #pragma unroll
        for (int j = 0; j < 8; j++) {
            int h = h0 + j;
            float s = bn_g[h] * rsqrtf(bn_v[h] + 1e-5f);
            o[j] = s * acc[j];
        }
        float4* dst = (float4*)(g_At + (size_t)(row - NB*NL)*HD + h0);
        dst[0] = make_float4(o[0], o[1], o[2], o[3]);
        dst[1] = make_float4(o[4], o[5], o[6], o[7]);
    }
}

// ---------------------------------------------------------------------------
// Pair kernel via mma.sync (HMMA bf16, 2-term split, 3 passes).
// R10: warp = m16 tile (16 pairs x 32 heads, D = 16 regs/thread).
// Block = 4 ligands x 32 proteins, 8 warps: warp w -> (lig w>>1, prot-half w&1).
// 48-reg target -> 5 blocks/SM; grid 1536 at half work per block.
// ---------------------------------------------------------------------------
#define THREADS 256
#define AT_P 136              // float pitch for At/Al staging (mod 32 == 8)

// smem float offsets — F_D overlaps [F_AT..) (operands dead after mainloop)
#define F_AT   0              // 32 x 136 = 4352
#define F_AL   4352           // 4 x 136 = 544
#define F_W    4896           // [kc 8][nc 4][lane 32] uint4 = 4096 floats
#define F_D    0              // 128 x 34 = 4352  (union)
#define F_BIAS 8992           // 32
#define F_PL   9024           // 4 x 4
#define F_PT   9040           // 32 x 4
#define SMF    9168           // floats -> 36672 bytes

__device__ __forceinline__ float wval(int n, int k, const float* __restrict__ wp,
                                      const float* __restrict__ ws,
                                      const float* __restrict__ wm) {
    if (n < 10) return wp[n*HD + k];
    if (n < 20) return ws[(n-10)*HD + k];
    if (n < 30) return wm[(n-20)*HD + k];
    return 0.0f;
}

__global__ void __launch_bounds__(THREADS, 5)
pair_kernel(const float* __restrict__ lig_pos, const float* __restrict__ pro_pos,
            const float* __restrict__ W_pi,  const float* __restrict__ b_pi,
            const float* __restrict__ W_sig, const float* __restrict__ b_sig,
            const float* __restrict__ W_mu,  const float* __restrict__ b_mu,
            float* __restrict__ out)
{
    extern __shared__ float sm[];
    const int tid  = threadIdx.x;
    const int w    = tid >> 5;           // 8 warps
    const int lane = tid & 31;
    const int r    = lane >> 2;          // 0..7
    const int q    = lane & 3;           // 0..3
    const int ligl = w >> 1;             // local ligand 0..3
    const int ph   = (w & 1) << 4;       // protein half offset: 0 or 16
    const int b    = blockIdx.z;
    const int l0   = blockIdx.y * 4;
    const int t0   = blockIdx.x * 32;

    // ---- stage At (32 rows) and Al (4 rows), fp32, pitch 136 ----
    {
        const float4* src = (const float4*)(g_At + (size_t)(b*NT + t0)*HD);
        float4* dst = (float4*)&sm[F_AT];          // pitch 34 float4
        #pragma unroll
        for (int i = 0; i < 4; i++) {
            int idx = tid + i*THREADS;              // < 1024
            dst[(idx >> 5)*34 + (idx & 31)] = src[idx];
        }
    }
    if (tid < 128) {   // Al: 4 rows x 32 float4
        const float4* src = (const float4*)(g_Al + (size_t)(b*NL + l0)*HD);
        float4* dst = (float4*)&sm[F_AL];
        dst[(tid >> 5)*34 + (tid & 31)] = src[tid];
    }
    // ---- pre-split W into per-lane B fragments: uint4 {hi0,hi1,lo0,lo1} ----
    {
        uint4* wd = (uint4*)&sm[F_W];
        #pragma unroll
        for (int e = 0; e < 4; e++) {
            int idx = tid + e*THREADS;              // < 1024 = [kc 8][nc 4][lane 32]
            int kc = idx >> 7, nc = (idx >> 5) & 3, ln = idx & 31;
            int n = nc*8 + (ln >> 2);
            int k = kc*16 + 2*(ln & 3);
            float w0 = wval(n, k,   W_pi, W_sig, W_mu);
            float w1 = wval(n, k+1, W_pi, W_sig, W_mu);
            float w8 = wval(n, k+8, W_pi, W_sig, W_mu);
            float w9 = wval(n, k+9, W_pi, W_sig, W_mu);
            uint32_t h0, lo0, h1, lo1;
            split2(w0, w1, h0, lo0);
            split2(w8, w9, h1, lo1);
            wd[idx] = make_uint4(h0, h1, lo0, lo1);
        }
    }
    if (tid < NG) {
        sm[F_BIAS + tid]      = b_pi[tid];
        sm[F_BIAS + 10 + tid] = b_sig[tid];
        sm[F_BIAS + 20 + tid] = b_mu[tid];
    }
    if (tid < 12) {
        int l = tid / 3, c = tid % 3;
        sm[F_PL + l*4 + c] = lig_pos[(size_t)(b*NL + l0 + l)*3 + c];
    }
    if (tid < 96) {
        int t = tid / 3, c = tid % 3;
        sm[F_PT + t*4 + c] = pro_pos[(size_t)(b*NT + t0 + t)*3 + c];
    }
    __syncthreads();

    // ---- mainloop: warp computes D[16 pairs][32 heads] ----
    float D[4][4];
    #pragma unroll
    for (int nc = 0; nc < 4; nc++)
        #pragma unroll
        for (int j = 0; j < 4; j++) D[nc][j] = 0.0f;

    const float* alr = &sm[F_AL + ligl*AT_P + 2*q];
    const float* atr = &sm[F_AT + (ph + r)*AT_P + 2*q];
    const uint4* wl4 = (const uint4*)&sm[F_W] + lane;

    #pragma unroll 2
    for (int kc = 0; kc < 8; kc++) {
        const int kb = kc*16;
        float2 L0 = *(const float2*)(alr + kb);
        float2 L8 = *(const float2*)(alr + kb + 8);
        uint32_t ah[4], av[4];
        {
            float2 t00 = *(const float2*)(atr + kb);
            float2 t08 = *(const float2*)(atr + kb + 8);
            float2 t80 = *(const float2*)(atr + 8*AT_P + kb);
            float2 t88 = *(const float2*)(atr + 8*AT_P + kb + 8);
            split2(elu1(t00.x + L0.x), elu1(t00.y + L0.y), ah[0], av[0]);
            split2(elu1(t80.x + L0.x), elu1(t80.y + L0.y), ah[1], av[1]);
            split2(elu1(t08.x + L8.x), elu1(t08.y + L8.y), ah[2], av[2]);
            split2(elu1(t88.x + L8.x), elu1(t88.y + L8.y), ah[3], av[3]);
        }
        #pragma unroll
        for (int nc = 0; nc < 4; nc++) {
            uint4 wv = wl4[(kc*4 + nc)*32];
            uint32_t bh[2] = {wv.x, wv.y};
            uint32_t bl[2] = {wv.z, wv.w};
            mma_bf16(D[nc], ah, bh);
            mma_bf16(D[nc], ah, bl);
            mma_bf16(D[nc], av, bh);
        }
    }

    // operands (At/Al/W) dead from here; D buffer overlaps them
    __syncthreads();

    // ---- D fragments -> smem (pair-major, pitch 34) ----
    {
        const int p = ligl*32 + ph + r;
        #pragma unroll
        for (int nc = 0; nc < 4; nc++) {
            *(float2*)&sm[F_D + p*34 + nc*8 + 2*q]     = make_float2(D[nc][0], D[nc][1]);
            *(float2*)&sm[F_D + (p+8)*34 + nc*8 + 2*q] = make_float2(D[nc][2], D[nc][3]);
        }
    }
    __syncthreads();

    // ---- per-pair epilogue (128 pairs; threads 0..127) ----
    if (tid < 128) {
        float* row = &sm[F_D + tid*34];
        float rr[30];
        #pragma unroll
        for (int g = 0; g < 30; g++) rr[g] = row[g];
        float y[10], mx = -1e30f;
        #pragma unroll
        for (int g = 0; g < NG; g++) { y[g] = rr[g] + sm[F_BIAS + g]; mx = fmaxf(mx, y[g]); }
        float ssum = 0.0f;
        #pragma unroll
        for (int g = 0; g < NG; g++) { y[g] = __expf(y[g] - mx); ssum += y[g]; }
        float inv = 1.0f / ssum;
        #pragma unroll
        for (int g = 0; g < NG; g++) row[g] = y[g]*inv;
        #pragma unroll
        for (int g = 0; g < NG; g++) row[10+g] = elu1(rr[10+g] + sm[F_BIAS + 10 + g]) + 1.1f;
        #pragma unroll
        for (int g = 0; g < NG; g++) row[20+g] = elu1(rr[20+g] + sm[F_BIAS + 20 + g]) + 1.0f;
        const int ll = tid >> 5, tl = tid & 31;
        float dx = sm[F_PL + ll*4]   - sm[F_PT + tl*4];
        float dy = sm[F_PL + ll*4+1] - sm[F_PT + tl*4+1];
        float dz = sm[F_PL + ll*4+2] - sm[F_PT + tl*4+2];
        row[30] = sqrtf(dx*dx + dy*dy + dz*dz);
    }
    __syncthreads();

    // ---- coalesced copy-out: pi / sigma / mu (3 x 4 ligs x 320 floats) ----
    #pragma unroll
    for (int i = 0; i < 15; i++) {
        int idx = tid + i*THREADS;          // exactly 3840 total
        int sec = idx / 1280;
        int rem = idx - sec*1280;
        int llc = rem / 320;
        int r2  = rem - llc*320;
        int t   = r2 / 10;
        int g   = r2 - t*10;
        size_t secoff = (sec == 0) ? (size_t)OFF_PI : (sec == 1) ? (size_t)OFF_SIG : (size_t)OFF_MU;
        size_t gaddr = secoff + ((size_t)((b*NL + l0 + llc)*NT) + t0 + t)*NG + g;
        out[gaddr] = sm[F_D + (llc*32 + t)*34 + sec*10 + g];
    }
    // dist + batch id
    if (tid < 128) {
        size_t pg = (size_t)((b*NL + l0 + (tid >> 5))*NT) + t0 + (tid & 31);
        out[OFF_D  + pg] = sm[F_D + tid*34 + 30];
        out[OFF_CB + pg] = (float)b;
    }
}

// ---------------------------------------------------------------------------
extern "C" void kernel_launch(void* const* d_in, const int* in_sizes, int n_in,
                              void* d_out, int out_size)
{
    (void)in_sizes; (void)n_in; (void)out_size;
    const float* lig_s   = (const float*)d_in[0];
    const float* lig_pos = (const float*)d_in[1];
    const float* pro_s   = (const float*)d_in[3];
    const float* pro_pos = (const float*)d_in[4];
    const float* W1      = (const float*)d_in[6];
    const float* b1      = (const float*)d_in[7];
    const float* bn_g    = (const float*)d_in[8];
    const float* bn_b    = (const float*)d_in[9];
    const float* bn_m    = (const float*)d_in[10];
    const float* bn_v    = (const float*)d_in[11];
    const float* W_pi    = (const float*)d_in[12];
    const float* b_pi    = (const float*)d_in[13];
    const float* W_sig   = (const float*)d_in[14];
    const float* b_sig   = (const float*)d_in[15];
    const float* W_mu    = (const float*)d_in[16];
    const float* b_mu    = (const float*)d_in[17];
    float* out = (float*)d_out;

    cudaFuncSetAttribute(precompute_kernel,
                         cudaFuncAttributeMaxDynamicSharedMemorySize, (int)PRE_SMEM);
    precompute_kernel<<<(NB*NL + NB*NT)/PRE_ROWS, PRE_THREADS, PRE_SMEM>>>(
        lig_s, pro_s, W1, b1, bn_g, bn_b, bn_m, bn_v);

    pair_kernel<<<dim3(NT/32, NL/4, NB), THREADS, SMF*sizeof(float)>>>(
        lig_pos, pro_pos, W_pi, b_pi, W_sig, b_sig, W_mu, b_mu, out);
}

// round 11
// speedup vs baseline: 1.5706x; 1.1471x over previous
#include <cuda_runtime.h>
#include <cuda_fp16.h>
#include <math.h>
#include <stdint.h>

#define NB 8
#define NL 48
#define NT 512
#define HD 128
#define NG 10
#define M_TOTAL (NB*NL*NT)          // 196608

#define OFF_PI  0
#define OFF_SIG (M_TOTAL*NG)
#define OFF_MU  (2*M_TOTAL*NG)
#define OFF_D   (3*M_TOTAL*NG)
#define OFF_CB  (3*M_TOTAL*NG + M_TOTAL)

// scratch (device globals: no allocation)
__device__ float g_Al[NB*NL*HD];    // 384 x 128
__device__ float g_At[NB*NT*HD];    // 4096 x 128

__device__ __forceinline__ float elu1(float x) {
    return x > 0.0f ? x : (__expf(x) - 1.0f);
}

// pack two fp32 into f16x2: {lo16 = e0, hi16 = e1}
__device__ __forceinline__ uint32_t cvt2h(float e0, float e1) {
    uint32_t r;
    asm("cvt.rn.f16x2.f32 %0, %1, %2;" : "=r"(r) : "f"(e1), "f"(e0));
    return r;
}

// warp-level fp16 MMA, d += a*b, fp32 accumulate (baseline PTX sm_80+)
__device__ __forceinline__ void mma_f16(float* d, const uint32_t* a, const uint32_t* b) {
    asm volatile("mma.sync.aligned.m16n8k16.row.col.f32.f16.f16.f32 "
        "{%0,%1,%2,%3}, {%4,%5,%6,%7}, {%8,%9}, {%0,%1,%2,%3};"
        : "+f"(d[0]), "+f"(d[1]), "+f"(d[2]), "+f"(d[3])
        : "r"(a[0]), "r"(a[1]), "r"(a[2]), "r"(a[3]), "r"(b[0]), "r"(b[1]));
}

// ---------------------------------------------------------------------------
// Precompute: A_l = s*(lig_s@W1^T + b1 - mean) + beta ;  A_t = s*(pro_s@W1^T)
// ---------------------------------------------------------------------------
#define PRE_ROWS 32
#define PRE_THREADS 512
#define XS_P  129
#define W1T_P 132
#define PRE_SMEM ((PRE_ROWS*XS_P + HD*W1T_P)*sizeof(float))   // 84096 B

__global__ void __launch_bounds__(PRE_THREADS)
precompute_kernel(const float* __restrict__ lig_s, const float* __restrict__ pro_s,
                  const float* __restrict__ W1,    const float* __restrict__ b1,
                  const float* __restrict__ bn_g,  const float* __restrict__ bn_b,
                  const float* __restrict__ bn_m,  const float* __restrict__ bn_v)
{
    extern __shared__ float sm[];
    float* Xs  = sm;                      // [32][129]
    float* W1t = sm + PRE_ROWS*XS_P;      // [128][132] transposed

    const int tid  = threadIdx.x;
    const int w    = tid >> 5;            // 0..15
    const int ln   = tid & 31;
    const int row0 = blockIdx.x * PRE_ROWS;
    const bool is_lig = (row0 < NB*NL);

    const float4* src = is_lig ? (const float4*)(lig_s + (size_t)row0*HD)
                               : (const float4*)(pro_s + (size_t)(row0 - NB*NL)*HD);
    #pragma unroll
    for (int i = 0; i < 2; i++) {
        int idx = tid + i*PRE_THREADS;    // < 1024
        float4 v = src[idx];
        int r = idx >> 5, c = (idx & 31) << 2;
        Xs[r*XS_P + c]   = v.x;
        Xs[r*XS_P + c+1] = v.y;
        Xs[r*XS_P + c+2] = v.z;
        Xs[r*XS_P + c+3] = v.w;
    }
    #pragma unroll
    for (int i = 0; i < (HD*HD)/PRE_THREADS; i++) {
        int idx = tid + i*PRE_THREADS;
        int h = idx >> 7, k = idx & (HD-1);
        W1t[k*W1T_P + h] = W1[idx];
    }
    __syncthreads();

    const int h0 = w << 3;
    const float* xrow = Xs + ln*XS_P;
    float acc[8];
    #pragma unroll
    for (int j = 0; j < 8; j++) acc[j] = 0.0f;

    #pragma unroll 4
    for (int k = 0; k < HD; k++) {
        float x = xrow[k];
        float4 wa = *(const float4*)(W1t + k*W1T_P + h0);      // uniform -> bcast
        float4 wb = *(const float4*)(W1t + k*W1T_P + h0 + 4);
        acc[0] = fmaf(x, wa.x, acc[0]);
        acc[1] = fmaf(x, wa.y, acc[1]);
        acc[2] = fmaf(x, wa.z, acc[2]);
        acc[3] = fmaf(x, wa.w, acc[3]);
        acc[4] = fmaf(x, wb.x, acc[4]);
        acc[5] = fmaf(x, wb.y, acc[5]);
        acc[6] = fmaf(x, wb.z, acc[6]);
        acc[7] = fmaf(x, wb.w, acc[7]);
    }

    const int row = row0 + ln;
    float o[8];
    if (is_lig) {
        #pragma unroll
        for (int j = 0; j < 8; j++) {
            int h = h0 + j;
            float s = bn_g[h] * rsqrtf(bn_v[h] + 1e-5f);
            o[j] = s * (acc[j] + b1[h] - bn_m[h]) + bn_b[h];
        }
        float4* dst = (float4*)(g_Al + (size_t)row*HD + h0);
        dst[0] = make_float4(o[0], o[1], o[2], o[3]);
        dst[1] = make_float4(o[4], o[5], o[6], o[7]);
    } else {
        #pragma unroll
        for (int j = 0; j < 8; j++) {
            int h = h0 + j;
            float s = bn_g[h] * rsqrtf(bn_v[h] + 1e-5f);
            o[j] = s * acc[j];
        }
        float4* dst = (float4*)(g_At + (size_t)(row - NB*NL)*HD + h0);
        dst[0] = make_float4(o[0], o[1], o[2], o[3]);
        dst[1] = make_float4(o[4], o[5], o[6], o[7]);
    }
}

// ---------------------------------------------------------------------------
// Pair kernel via mma.sync (HMMA fp16, SINGLE pass, fp32 accumulate).
// R11: warp = 16 pairs x 32 heads (D = 16 regs). Block = 4 lig x 32 prot.
// fp16 (11 mantissa bits) single-pass: 4 MMA/kc (was 12), cvt.f16x2 (was
// split2), W fragments uint2. Predicted rel_err ~2e-4 (<1e-3).
// ---------------------------------------------------------------------------
#define THREADS 256
#define AT_P 136              // float pitch for At/Al staging (mod 32 == 8)

// smem float offsets — F_D overlaps [F_AT..) (operands dead after mainloop)
#define F_AT   0              // 32 x 136 = 4352
#define F_AL   4352           // 4 x 136 = 544
#define F_W    4896           // [kc 8][nc 4][lane 32] uint2 = 2048 floats
#define F_D    0              // 128 x 34 = 4352  (union)
#define F_BIAS 6944           // 32
#define F_PL   6976           // 4 x 4
#define F_PT   6992           // 32 x 4
#define SMF    7120           // floats -> 28480 bytes

__device__ __forceinline__ float wval(int n, int k, const float* __restrict__ wp,
                                      const float* __restrict__ ws,
                                      const float* __restrict__ wm) {
    if (n < 10) return wp[n*HD + k];
    if (n < 20) return ws[(n-10)*HD + k];
    if (n < 30) return wm[(n-20)*HD + k];
    return 0.0f;
}

__global__ void __launch_bounds__(THREADS, 5)
pair_kernel(const float* __restrict__ lig_pos, const float* __restrict__ pro_pos,
            const float* __restrict__ W_pi,  const float* __restrict__ b_pi,
            const float* __restrict__ W_sig, const float* __restrict__ b_sig,
            const float* __restrict__ W_mu,  const float* __restrict__ b_mu,
            float* __restrict__ out)
{
    extern __shared__ float sm[];
    const int tid  = threadIdx.x;
    const int w    = tid >> 5;           // 8 warps
    const int lane = tid & 31;
    const int r    = lane >> 2;          // 0..7
    const int q    = lane & 3;           // 0..3
    const int ligl = w >> 1;             // local ligand 0..3
    const int ph   = (w & 1) << 4;       // protein half offset: 0 or 16
    const int b    = blockIdx.z;
    const int l0   = blockIdx.y * 4;
    const int t0   = blockIdx.x * 32;

    // ---- stage At (32 rows) and Al (4 rows), fp32, pitch 136 ----
    {
        const float4* src = (const float4*)(g_At + (size_t)(b*NT + t0)*HD);
        float4* dst = (float4*)&sm[F_AT];          // pitch 34 float4
        #pragma unroll
        for (int i = 0; i < 4; i++) {
            int idx = tid + i*THREADS;              // < 1024
            dst[(idx >> 5)*34 + (idx & 31)] = src[idx];
        }
    }
    if (tid < 128) {   // Al: 4 rows x 32 float4
        const float4* src = (const float4*)(g_Al + (size_t)(b*NL + l0)*HD);
        float4* dst = (float4*)&sm[F_AL];
        dst[(tid >> 5)*34 + (tid & 31)] = src[tid];
    }
    // ---- pre-convert W into per-lane fp16 B fragments: uint2 {b0, b1} ----
    {
        uint2* wd = (uint2*)&sm[F_W];
        #pragma unroll
        for (int e = 0; e < 4; e++) {
            int idx = tid + e*THREADS;              // < 1024 = [kc 8][nc 4][lane 32]
            int kc = idx >> 7, nc = (idx >> 5) & 3, ln = idx & 31;
            int n = nc*8 + (ln >> 2);
            int k = kc*16 + 2*(ln & 3);
            float w0 = wval(n, k,   W_pi, W_sig, W_mu);
            float w1 = wval(n, k+1, W_pi, W_sig, W_mu);
            float w8 = wval(n, k+8, W_pi, W_sig, W_mu);
            float w9 = wval(n, k+9, W_pi, W_sig, W_mu);
            wd[idx] = make_uint2(cvt2h(w0, w1), cvt2h(w8, w9));
        }
    }
    if (tid < NG) {
        sm[F_BIAS + tid]      = b_pi[tid];
        sm[F_BIAS + 10 + tid] = b_sig[tid];
        sm[F_BIAS + 20 + tid] = b_mu[tid];
    }
    if (tid < 12) {
        int l = tid / 3, c = tid % 3;
        sm[F_PL + l*4 + c] = lig_pos[(size_t)(b*NL + l0 + l)*3 + c];
    }
    if (tid < 96) {
        int t = tid / 3, c = tid % 3;
        sm[F_PT + t*4 + c] = pro_pos[(size_t)(b*NT + t0 + t)*3 + c];
    }
    __syncthreads();

    // ---- mainloop: warp computes D[16 pairs][32 heads] ----
    float D[4][4];
    #pragma unroll
    for (int nc = 0; nc < 4; nc++)
        #pragma unroll
        for (int j = 0; j < 4; j++) D[nc][j] = 0.0f;

    const float* alr = &sm[F_AL + ligl*AT_P + 2*q];
    const float* atr = &sm[F_AT + (ph + r)*AT_P + 2*q];
    const uint2* wl2 = (const uint2*)&sm[F_W] + lane;

    #pragma unroll 2
    for (int kc = 0; kc < 8; kc++) {
        const int kb = kc*16;
        float2 L0 = *(const float2*)(alr + kb);
        float2 L8 = *(const float2*)(alr + kb + 8);
        uint32_t a[4];
        {
            float2 t00 = *(const float2*)(atr + kb);
            float2 t08 = *(const float2*)(atr + kb + 8);
            float2 t80 = *(const float2*)(atr + 8*AT_P + kb);
            float2 t88 = *(const float2*)(atr + 8*AT_P + kb + 8);
            a[0] = cvt2h(elu1(t00.x + L0.x), elu1(t00.y + L0.y));
            a[1] = cvt2h(elu1(t80.x + L0.x), elu1(t80.y + L0.y));
            a[2] = cvt2h(elu1(t08.x + L8.x), elu1(t08.y + L8.y));
            a[3] = cvt2h(elu1(t88.x + L8.x), elu1(t88.y + L8.y));
        }
        #pragma unroll
        for (int nc = 0; nc < 4; nc++) {
            uint2 wv = wl2[(kc*4 + nc)*32];
            uint32_t bb[2] = {wv.x, wv.y};
            mma_f16(D[nc], a, bb);
        }
    }

    // operands (At/Al/W) dead from here; D buffer overlaps them
    __syncthreads();

    // ---- D fragments -> smem (pair-major, pitch 34) ----
    {
        const int p = ligl*32 + ph + r;
        #pragma unroll
        for (int nc = 0; nc < 4; nc++) {
            *(float2*)&sm[F_D + p*34 + nc*8 + 2*q]     = make_float2(D[nc][0], D[nc][1]);
            *(float2*)&sm[F_D + (p+8)*34 + nc*8 + 2*q] = make_float2(D[nc][2], D[nc][3]);
        }
    }
    __syncthreads();

    // ---- per-pair epilogue (128 pairs; threads 0..127) ----
    if (tid < 128) {
        float* row = &sm[F_D + tid*34];
        float rr[30];
        #pragma unroll
        for (int g = 0; g < 30; g++) rr[g] = row[g];
        float y[10], mx = -1e30f;
        #pragma unroll
        for (int g = 0; g < NG; g++) { y[g] = rr[g] + sm[F_BIAS + g]; mx = fmaxf(mx, y[g]); }
        float ssum = 0.0f;
        #pragma unroll
        for (int g = 0; g < NG; g++) { y[g] = __expf(y[g] - mx); ssum += y[g]; }
        float inv = 1.0f / ssum;
        #pragma unroll
        for (int g = 0; g < NG; g++) row[g] = y[g]*inv;
        #pragma unroll
        for (int g = 0; g < NG; g++) row[10+g] = elu1(rr[10+g] + sm[F_BIAS + 10 + g]) + 1.1f;
        #pragma unroll
        for (int g = 0; g < NG; g++) row[20+g] = elu1(rr[20+g] + sm[F_BIAS + 20 + g]) + 1.0f;
        const int ll = tid >> 5, tl = tid & 31;
        float dx = sm[F_PL + ll*4]   - sm[F_PT + tl*4];
        float dy = sm[F_PL + ll*4+1] - sm[F_PT + tl*4+1];
        float dz = sm[F_PL + ll*4+2] - sm[F_PT + tl*4+2];
        row[30] = sqrtf(dx*dx + dy*dy + dz*dz);
    }
    __syncthreads();

    // ---- coalesced copy-out: pi / sigma / mu (3 x 4 ligs x 320 floats) ----
    #pragma unroll
    for (int i = 0; i < 15; i++) {
        int idx = tid + i*THREADS;          // exactly 3840 total
        int sec = idx / 1280;
        int rem = idx - sec*1280;
        int llc = rem / 320;
        int r2  = rem - llc*320;
        int t   = r2 / 10;
        int g   = r2 - t*10;
        size_t secoff = (sec == 0) ? (size_t)OFF_PI : (sec == 1) ? (size_t)OFF_SIG : (size_t)OFF_MU;
        size_t gaddr = secoff + ((size_t)((b*NL + l0 + llc)*NT) + t0 + t)*NG + g;
        out[gaddr] = sm[F_D + (llc*32 + t)*34 + sec*10 + g];
    }
    // dist + batch id
    if (tid < 128) {
        size_t pg = (size_t)((b*NL + l0 + (tid >> 5))*NT) + t0 + (tid & 31);
        out[OFF_D  + pg] = sm[F_D + tid*34 + 30];
        out[OFF_CB + pg] = (float)b;
    }
}

// ---------------------------------------------------------------------------
extern "C" void kernel_launch(void* const* d_in, const int* in_sizes, int n_in,
                              void* d_out, int out_size)
{
    (void)in_sizes; (void)n_in; (void)out_size;
    const float* lig_s   = (const float*)d_in[0];
    const float* lig_pos = (const float*)d_in[1];
    const float* pro_s   = (const float*)d_in[3];
    const float* pro_pos = (const float*)d_in[4];
    const float* W1      = (const float*)d_in[6];
    const float* b1      = (const float*)d_in[7];
    const float* bn_g    = (const float*)d_in[8];
    const float* bn_b    = (const float*)d_in[9];
    const float* bn_m    = (const float*)d_in[10];
    const float* bn_v    = (const float*)d_in[11];
    const float* W_pi    = (const float*)d_in[12];
    const float* b_pi    = (const float*)d_in[13];
    const float* W_sig   = (const float*)d_in[14];
    const float* b_sig   = (const float*)d_in[15];
    const float* W_mu    = (const float*)d_in[16];
    const float* b_mu    = (const float*)d_in[17];
    float* out = (float*)d_out;

    cudaFuncSetAttribute(precompute_kernel,
                         cudaFuncAttributeMaxDynamicSharedMemorySize, (int)PRE_SMEM);
    precompute_kernel<<<(NB*NL + NB*NT)/PRE_ROWS, PRE_THREADS, PRE_SMEM>>>(
        lig_s, pro_s, W1, b1, bn_g, bn_b, bn_m, bn_v);

    pair_kernel<<<dim3(NT/32, NL/4, NB), THREADS, SMF*sizeof(float)>>>(
        lig_pos, pro_pos, W_pi, b_pi, W_sig, b_sig, W_mu, b_mu, out);
}

// round 12
// speedup vs baseline: 1.8288x; 1.1644x over previous
#include <cuda_runtime.h>
#include <cuda_fp16.h>
#include <math.h>
#include <stdint.h>

#define NB 8
#define NL 48
#define NT 512
#define HD 128
#define NG 10
#define M_TOTAL (NB*NL*NT)          // 196608

#define OFF_PI  0
#define OFF_SIG (M_TOTAL*NG)
#define OFF_MU  (2*M_TOTAL*NG)
#define OFF_D   (3*M_TOTAL*NG)
#define OFF_CB  (3*M_TOTAL*NG + M_TOTAL)

// scratch (device globals: no allocation)
__device__ float g_Al[NB*NL*HD];    // 384 x 128
__device__ float g_At[NB*NT*HD];    // 4096 x 128
__device__ uint2 g_Wfrag[1024];     // fp16 W fragments [kc 8][nc 4][lane 32]

__device__ __forceinline__ float elu1(float x) {
    return x > 0.0f ? x : (__expf(x) - 1.0f);
}

// pack two fp32 into f16x2: {lo16 = e0, hi16 = e1}
__device__ __forceinline__ uint32_t cvt2h(float e0, float e1) {
    uint32_t r;
    asm("cvt.rn.f16x2.f32 %0, %1, %2;" : "=r"(r) : "f"(e1), "f"(e0));
    return r;
}

// warp-level fp16 MMA, d += a*b, fp32 accumulate (baseline PTX sm_80+)
__device__ __forceinline__ void mma_f16(float* d, const uint32_t* a, const uint32_t* b) {
    asm volatile("mma.sync.aligned.m16n8k16.row.col.f32.f16.f16.f32 "
        "{%0,%1,%2,%3}, {%4,%5,%6,%7}, {%8,%9}, {%0,%1,%2,%3};"
        : "+f"(d[0]), "+f"(d[1]), "+f"(d[2]), "+f"(d[3])
        : "r"(a[0]), "r"(a[1]), "r"(a[2]), "r"(a[3]), "r"(b[0]), "r"(b[1]));
}

__device__ __forceinline__ float wval(int n, int k, const float* __restrict__ wp,
                                      const float* __restrict__ ws,
                                      const float* __restrict__ wm) {
    if (n < 10) return wp[n*HD + k];
    if (n < 20) return ws[(n-10)*HD + k];
    if (n < 30) return wm[(n-20)*HD + k];
    return 0.0f;
}

// ---------------------------------------------------------------------------
// Precompute: A_l = s*(lig_s@W1^T + b1 - mean) + beta ;  A_t = s*(pro_s@W1^T)
// Last block additionally converts the 3 head-weight matrices into fp16
// per-lane MMA B-fragments (g_Wfrag), done ONCE for the whole grid.
// ---------------------------------------------------------------------------
#define PRE_ROWS 32
#define PRE_THREADS 512
#define XS_P  129
#define W1T_P 132
#define PRE_SMEM ((PRE_ROWS*XS_P + HD*W1T_P)*sizeof(float))   // 84096 B
#define PRE_ROWBLOCKS ((NB*NL + NB*NT)/PRE_ROWS)              // 140

__global__ void __launch_bounds__(PRE_THREADS)
precompute_kernel(const float* __restrict__ lig_s, const float* __restrict__ pro_s,
                  const float* __restrict__ W1,    const float* __restrict__ b1,
                  const float* __restrict__ bn_g,  const float* __restrict__ bn_b,
                  const float* __restrict__ bn_m,  const float* __restrict__ bn_v,
                  const float* __restrict__ W_pi,  const float* __restrict__ W_sig,
                  const float* __restrict__ W_mu)
{
    const int tid = threadIdx.x;

    // ---- W-fragment block (once per grid) ----
    if (blockIdx.x == PRE_ROWBLOCKS) {
        for (int idx = tid; idx < 1024; idx += PRE_THREADS) {
            int kc = idx >> 7, nc = (idx >> 5) & 3, ln = idx & 31;
            int n = nc*8 + (ln >> 2);
            int k = kc*16 + 2*(ln & 3);
            float w0 = wval(n, k,   W_pi, W_sig, W_mu);
            float w1 = wval(n, k+1, W_pi, W_sig, W_mu);
            float w8 = wval(n, k+8, W_pi, W_sig, W_mu);
            float w9 = wval(n, k+9, W_pi, W_sig, W_mu);
            g_Wfrag[idx] = make_uint2(cvt2h(w0, w1), cvt2h(w8, w9));
        }
        return;
    }

    extern __shared__ float sm[];
    float* Xs  = sm;                      // [32][129]
    float* W1t = sm + PRE_ROWS*XS_P;      // [128][132] transposed

    const int w    = tid >> 5;            // 0..15
    const int ln   = tid & 31;
    const int row0 = blockIdx.x * PRE_ROWS;
    const bool is_lig = (row0 < NB*NL);

    const float4* src = is_lig ? (const float4*)(lig_s + (size_t)row0*HD)
                               : (const float4*)(pro_s + (size_t)(row0 - NB*NL)*HD);
    #pragma unroll
    for (int i = 0; i < 2; i++) {
        int idx = tid + i*PRE_THREADS;    // < 1024
        float4 v = src[idx];
        int r = idx >> 5, c = (idx & 31) << 2;
        Xs[r*XS_P + c]   = v.x;
        Xs[r*XS_P + c+1] = v.y;
        Xs[r*XS_P + c+2] = v.z;
        Xs[r*XS_P + c+3] = v.w;
    }
    #pragma unroll
    for (int i = 0; i < (HD*HD)/PRE_THREADS; i++) {
        int idx = tid + i*PRE_THREADS;
        int h = idx >> 7, k = idx & (HD-1);
        W1t[k*W1T_P + h] = W1[idx];
    }
    __syncthreads();

    const int h0 = w << 3;
    const float* xrow = Xs + ln*XS_P;
    float acc[8];
    #pragma unroll
    for (int j = 0; j < 8; j++) acc[j] = 0.0f;

    #pragma unroll 4
    for (int k = 0; k < HD; k++) {
        float x = xrow[k];
        float4 wa = *(const float4*)(W1t + k*W1T_P + h0);      // uniform -> bcast
        float4 wb = *(const float4*)(W1t + k*W1T_P + h0 + 4);
        acc[0] = fmaf(x, wa.x, acc[0]);
        acc[1] = fmaf(x, wa.y, acc[1]);
        acc[2] = fmaf(x, wa.z, acc[2]);
        acc[3] = fmaf(x, wa.w, acc[3]);
        acc[4] = fmaf(x, wb.x, acc[4]);
        acc[5] = fmaf(x, wb.y, acc[5]);
        acc[6] = fmaf(x, wb.z, acc[6]);
        acc[7] = fmaf(x, wb.w, acc[7]);
    }

    const int row = row0 + ln;
    float o[8];
    if (is_lig) {
        #pragma unroll
        for (int j = 0; j < 8; j++) {
            int h = h0 + j;
            float s = bn_g[h] * rsqrtf(bn_v[h] + 1e-5f);
            o[j] = s * (acc[j] + b1[h] - bn_m[h]) + bn_b[h];
        }
        float4* dst = (float4*)(g_Al + (size_t)row*HD + h0);
        dst[0] = make_float4(o[0], o[1], o[2], o[3]);
        dst[1] = make_float4(o[4], o[5], o[6], o[7]);
    } else {
        #pragma unroll
        for (int j = 0; j < 8; j++) {
            int h = h0 + j;
            float s = bn_g[h] * rsqrtf(bn_v[h] + 1e-5f);
            o[j] = s * acc[j];
        }
        float4* dst = (float4*)(g_At + (size_t)(row - NB*NL)*HD + h0);
        dst[0] = make_float4(o[0], o[1], o[2], o[3]);
        dst[1] = make_float4(o[4], o[5], o[6], o[7]);
    }
}

// ---------------------------------------------------------------------------
// Pair kernel via mma.sync (HMMA fp16, single pass, fp32 accumulate).
// R12: W fragments preconverted (8KB bulk copy); direct register->gmem
// epilogue stores (no copy-out loop / divisions); epilogue split over all
// 256 threads (lower half: softmax+dist, upper half: sigma+mu).
// ---------------------------------------------------------------------------
#define THREADS 256
#define AT_P 136              // float pitch for At/Al staging (mod 32 == 8)

// smem float offsets — F_D overlaps [F_AT..) (operands dead after mainloop)
#define F_AT   0              // 32 x 136 = 4352
#define F_AL   4352           // 4 x 136 = 544
#define F_W    4896           // [kc 8][nc 4][lane 32] uint2 = 2048 floats
#define F_D    0              // 128 x 34 = 4352  (union)
#define F_BIAS 6944           // 32
#define F_PL   6976           // 4 x 4
#define F_PT   6992           // 32 x 4
#define SMF    7120           // floats -> 28480 bytes

__global__ void __launch_bounds__(THREADS, 5)
pair_kernel(const float* __restrict__ lig_pos, const float* __restrict__ pro_pos,
            const float* __restrict__ b_pi, const float* __restrict__ b_sig,
            const float* __restrict__ b_mu,
            float* __restrict__ out)
{
    extern __shared__ float sm[];
    const int tid  = threadIdx.x;
    const int w    = tid >> 5;           // 8 warps
    const int lane = tid & 31;
    const int r    = lane >> 2;          // 0..7
    const int q    = lane & 3;           // 0..3
    const int ligl = w >> 1;             // local ligand 0..3
    const int ph   = (w & 1) << 4;       // protein half offset: 0 or 16
    const int b    = blockIdx.z;
    const int l0   = blockIdx.y * 4;
    const int t0   = blockIdx.x * 32;

    // ---- stage At (32 rows) and Al (4 rows), fp32, pitch 136 ----
    {
        const float4* src = (const float4*)(g_At + (size_t)(b*NT + t0)*HD);
        float4* dst = (float4*)&sm[F_AT];          // pitch 34 float4
        #pragma unroll
        for (int i = 0; i < 4; i++) {
            int idx = tid + i*THREADS;              // < 1024
            dst[(idx >> 5)*34 + (idx & 31)] = src[idx];
        }
    }
    if (tid < 128) {   // Al: 4 rows x 32 float4
        const float4* src = (const float4*)(g_Al + (size_t)(b*NL + l0)*HD);
        float4* dst = (float4*)&sm[F_AL];
        dst[(tid >> 5)*34 + (tid & 31)] = src[tid];
    }
    // ---- bulk-copy preconverted W fragments (8 KB) ----
    {
        const uint4* src4 = (const uint4*)g_Wfrag;   // 512 uint4
        uint4* dst4 = (uint4*)&sm[F_W];
        dst4[tid]       = src4[tid];
        dst4[tid + 256] = src4[tid + 256];
    }
    if (tid < NG) {
        sm[F_BIAS + tid]      = b_pi[tid];
        sm[F_BIAS + 10 + tid] = b_sig[tid];
        sm[F_BIAS + 20 + tid] = b_mu[tid];
    }
    if (tid < 12) {
        int l = tid / 3, c = tid % 3;
        sm[F_PL + l*4 + c] = lig_pos[(size_t)(b*NL + l0 + l)*3 + c];
    }
    if (tid < 96) {
        int t = tid / 3, c = tid % 3;
        sm[F_PT + t*4 + c] = pro_pos[(size_t)(b*NT + t0 + t)*3 + c];
    }
    __syncthreads();

    // ---- mainloop: warp computes D[16 pairs][32 heads] ----
    float D[4][4];
    #pragma unroll
    for (int nc = 0; nc < 4; nc++)
        #pragma unroll
        for (int j = 0; j < 4; j++) D[nc][j] = 0.0f;

    const float* alr = &sm[F_AL + ligl*AT_P + 2*q];
    const float* atr = &sm[F_AT + (ph + r)*AT_P + 2*q];
    const uint2* wl2 = (const uint2*)&sm[F_W] + lane;

    #pragma unroll 2
    for (int kc = 0; kc < 8; kc++) {
        const int kb = kc*16;
        float2 L0 = *(const float2*)(alr + kb);
        float2 L8 = *(const float2*)(alr + kb + 8);
        uint32_t a[4];
        {
            float2 t00 = *(const float2*)(atr + kb);
            float2 t08 = *(const float2*)(atr + kb + 8);
            float2 t80 = *(const float2*)(atr + 8*AT_P + kb);
            float2 t88 = *(const float2*)(atr + 8*AT_P + kb + 8);
            a[0] = cvt2h(elu1(t00.x + L0.x), elu1(t00.y + L0.y));
            a[1] = cvt2h(elu1(t80.x + L0.x), elu1(t80.y + L0.y));
            a[2] = cvt2h(elu1(t08.x + L8.x), elu1(t08.y + L8.y));
            a[3] = cvt2h(elu1(t88.x + L8.x), elu1(t88.y + L8.y));
        }
        #pragma unroll
        for (int nc = 0; nc < 4; nc++) {
            uint2 wv = wl2[(kc*4 + nc)*32];
            uint32_t bb[2] = {wv.x, wv.y};
            mma_f16(D[nc], a, bb);
        }
    }

    // operands (At/Al/W) dead from here; D buffer overlaps them
    __syncthreads();

    // ---- D fragments -> smem (pair-major, pitch 34) ----
    {
        const int p = ligl*32 + ph + r;
        #pragma unroll
        for (int nc = 0; nc < 4; nc++) {
            *(float2*)&sm[F_D + p*34 + nc*8 + 2*q]     = make_float2(D[nc][0], D[nc][1]);
            *(float2*)&sm[F_D + (p+8)*34 + nc*8 + 2*q] = make_float2(D[nc][2], D[nc][3]);
        }
    }
    __syncthreads();

    // ---- split epilogue: tid<128 -> softmax+dist; tid>=128 -> sigma+mu ----
    {
        const int p  = tid & 127;
        const int ll = p >> 5, tl = p & 31;
        const float* row = &sm[F_D + p*34];
        const size_t pg = (size_t)((b*NL + l0 + ll)*NT) + t0 + tl;
        if (tid < 128) {
            float y[10], mx = -1e30f;
            #pragma unroll
            for (int g = 0; g < NG; g++) { y[g] = row[g] + sm[F_BIAS + g]; mx = fmaxf(mx, y[g]); }
            float ssum = 0.0f;
            #pragma unroll
            for (int g = 0; g < NG; g++) { y[g] = __expf(y[g] - mx); ssum += y[g]; }
            float inv = 1.0f / ssum;
            float2* po = (float2*)(out + OFF_PI + pg*NG);
            #pragma unroll
            for (int g = 0; g < 5; g++) po[g] = make_float2(y[2*g]*inv, y[2*g+1]*inv);
            float dx = sm[F_PL + ll*4]   - sm[F_PT + tl*4];
            float dy = sm[F_PL + ll*4+1] - sm[F_PT + tl*4+1];
            float dz = sm[F_PL + ll*4+2] - sm[F_PT + tl*4+2];
            out[OFF_D  + pg] = sqrtf(dx*dx + dy*dy + dz*dz);
            out[OFF_CB + pg] = (float)b;
        } else {
            float2* so = (float2*)(out + OFF_SIG + pg*NG);
            #pragma unroll
            for (int g = 0; g < 5; g++) {
                float s0 = elu1(row[10+2*g]   + sm[F_BIAS + 10 + 2*g])   + 1.1f;
                float s1 = elu1(row[10+2*g+1] + sm[F_BIAS + 10 + 2*g+1]) + 1.1f;
                so[g] = make_float2(s0, s1);
            }
            float2* mo = (float2*)(out + OFF_MU + pg*NG);
            #pragma unroll
            for (int g = 0; g < 5; g++) {
                float m0 = elu1(row[20+2*g]   + sm[F_BIAS + 20 + 2*g])   + 1.0f;
                float m1 = elu1(row[20+2*g+1] + sm[F_BIAS + 20 + 2*g+1]) + 1.0f;
                mo[g] = make_float2(m0, m1);
            }
        }
    }
}

// ---------------------------------------------------------------------------
extern "C" void kernel_launch(void* const* d_in, const int* in_sizes, int n_in,
                              void* d_out, int out_size)
{
    (void)in_sizes; (void)n_in; (void)out_size;
    const float* lig_s   = (const float*)d_in[0];
    const float* lig_pos = (const float*)d_in[1];
    const float* pro_s   = (const float*)d_in[3];
    const float* pro_pos = (const float*)d_in[4];
    const float* W1      = (const float*)d_in[6];
    const float* b1      = (const float*)d_in[7];
    const float* bn_g    = (const float*)d_in[8];
    const float* bn_b    = (const float*)d_in[9];
    const float* bn_m    = (const float*)d_in[10];
    const float* bn_v    = (const float*)d_in[11];
    const float* W_pi    = (const float*)d_in[12];
    const float* b_pi    = (const float*)d_in[13];
    const float* W_sig   = (const float*)d_in[14];
    const float* b_sig   = (const float*)d_in[15];
    const float* W_mu    = (const float*)d_in[16];
    const float* b_mu    = (const float*)d_in[17];
    float* out = (float*)d_out;

    cudaFuncSetAttribute(precompute_kernel,
                         cudaFuncAttributeMaxDynamicSharedMemorySize, (int)PRE_SMEM);
    precompute_kernel<<<PRE_ROWBLOCKS + 1, PRE_THREADS, PRE_SMEM>>>(
        lig_s, pro_s, W1, b1, bn_g, bn_b, bn_m, bn_v, W_pi, W_sig, W_mu);

    pair_kernel<<<dim3(NT/32, NL/4, NB), THREADS, SMF*sizeof(float)>>>(
        lig_pos, pro_pos, b_pi, b_sig, b_mu, out);
}